// round 14
// baseline (speedup 1.0000x reference)
#include <cuda_runtime.h>
#include <cuda_bf16.h>
#include <cuda_fp16.h>
#include <cstdint>

// Problem constants
#define NB   8
#define NN   8192
#define CIN  64
#define COUT 128
#define KNB  16
#define MM   16
#define NPTS (NB*NN)            // 65536
#define AGGK (CIN*MM)           // 1024

// -------- device scratch --------
// Chunk-major, PRE-SWIZZLED (SWZ128 within each [128 rows x 128B] tile):
//   g_aggc : [16 chunks][NPTS][64 halves]  (134 MB)
//   g_WpTh : [16 chunks][COUT][64 halves]  (256 KB)
__device__ __half g_aggc[(size_t)16 * NPTS * 64];
__device__ __half g_WpTh[(size_t)16 * COUT * 64];
__device__ float4 g_pts4[NPTS];
__device__ float  g_A1[32*3];
__device__ float  g_c1[32];

#define SWZ(o) ((o) ^ (((o) >> 3) & 0x70))

// ============================================================
// PTX helpers
// ============================================================
__device__ __forceinline__ uint32_t smem_u32(const void* p) {
    uint32_t a;
    asm("{ .reg .u64 t; cvta.to.shared.u64 t, %1; cvt.u32.u64 %0, t; }" : "=r"(a) : "l"(p));
    return a;
}
__device__ __forceinline__ uint32_t packh2(float a, float b) {
    __half2 h = __floats2half2_rn(a, b);
    return *(uint32_t*)&h;
}
#define MBAR_INIT(a, c) asm volatile("mbarrier.init.shared.b64 [%0], %1;" :: "r"(a), "r"(c) : "memory")
#define MBAR_EXPECT_TX(a, bytes) \
    asm volatile("mbarrier.arrive.expect_tx.shared.b64 _, [%0], %1;" :: "r"(a), "r"(bytes) : "memory")
#define MBAR_WAIT(a, ph) do {                                                    \
    uint32_t _m = (a), _p = (ph), _d;                                            \
    asm volatile("{ .reg .pred p; mbarrier.try_wait.parity.acquire.cta.shared::cta.b64 p, [%1], %2; selp.b32 %0,1,0,p; }" \
                 : "=r"(_d) : "r"(_m), "r"(_p) : "memory");                      \
    if (!_d) {                                                                   \
        asm volatile("{ .reg .pred P1; WL_%=: mbarrier.try_wait.parity.acquire.cta.shared::cta.b64 P1, [%0], %1, 0x989680;\n\t" \
                     "@P1 bra.uni WD_%=; bra.uni WL_%=; WD_%=: }"                \
                     :: "r"(_m), "r"(_p) : "memory");                            \
    }                                                                            \
} while (0)
#define CP_BULK(dst, src, bytes, mbar) \
    asm volatile("cp.async.bulk.shared::cluster.global.mbarrier::complete_tx::bytes [%0], [%1], %2, [%3];" \
                 :: "r"(dst), "l"(src), "r"(bytes), "r"(mbar) : "memory")

__device__ __forceinline__ void ldsm_x4(uint32_t& r0, uint32_t& r1, uint32_t& r2, uint32_t& r3,
                                        uint32_t addr) {
    asm volatile("ldmatrix.sync.aligned.m8n8.x4.shared.b16 {%0,%1,%2,%3}, [%4];"
                 : "=r"(r0), "=r"(r1), "=r"(r2), "=r"(r3) : "r"(addr));
}
__device__ __forceinline__ void mma_f16(float c[4], const uint32_t a[4], const uint32_t b[2]) {
    asm volatile(
        "mma.sync.aligned.m16n8k16.row.col.f32.f16.f16.f32 "
        "{%0,%1,%2,%3}, {%4,%5,%6,%7}, {%8,%9}, {%0,%1,%2,%3};"
        : "+f"(c[0]), "+f"(c[1]), "+f"(c[2]), "+f"(c[3])
        : "r"(a[0]), "r"(a[1]), "r"(a[2]), "r"(a[3]), "r"(b[0]), "r"(b[1]));
}

// ============================================================
// Prep (fused): weight -> chunk-major pre-swizzled fp16; pts4 pack;
// layer-1 affine collapse (block 0).
// ============================================================
__global__ void prep_kernel(const float* __restrict__ weight,
                            const float* __restrict__ input_pts,
                            const float* __restrict__ l1_w,
                            const float* __restrict__ l1_b,
                            const float* __restrict__ centers)
{
    int e = blockIdx.x * blockDim.x + threadIdx.x;   // 0 .. 131071

    if (e < AGGK * COUT) {
        int n  = e & 127;
        int cm = e >> 7;
        int m  = cm & 15;
        int c  = cm >> 4;
        int gg = c & 7, ih = (c >> 3) & 1, mt = c >> 4;
        int nt = m >> 3, t4 = (m >> 1) & 3, bb = m & 1;
        int u  = ((mt*2 + ih)*2 + nt)*32 + gg*4 + t4;
        int kc = u >> 5;
        int ln = u & 31;
        uint32_t o = ((uint32_t)n << 7) + ((uint32_t)ln << 2) + ((uint32_t)bb << 1);
        o = SWZ(o);
        *(__half*)((char*)g_WpTh + (size_t)kc*COUT*128 + o) = __float2half_rn(weight[e]);
    }

    if (e < NPTS) {
        g_pts4[e] = make_float4(input_pts[e*3+0], input_pts[e*3+1],
                                input_pts[e*3+2], 0.f);
    }

    if (blockIdx.x == 0 && threadIdx.x < 32) {
        int o = threadIdx.x;
        float a0 = 0.f, a1 = 0.f, a2 = 0.f;
        float c = l1_b[o];
        #pragma unroll
        for (int m = 0; m < MM; m++) {
            float w0 = l1_w[o*48 + 0*16 + m];
            float w1 = l1_w[o*48 + 1*16 + m];
            float w2 = l1_w[o*48 + 2*16 + m];
            a0 += w0; a1 += w1; a2 += w2;
            c -= w0 * centers[0*16 + m];
            c -= w1 * centers[1*16 + m];
            c -= w2 * centers[2*16 + m];
        }
        g_A1[o*3+0] = a0; g_A1[o*3+1] = a1; g_A1[o*3+2] = a2;
        g_c1[o] = c;
    }
}

// ============================================================
// Kernel A (v7): as R13 but stores to chunk-major pre-swizzled g_aggc.
// ============================================================
#define PH1 40
#define PH2 24
#define PDD 20

__global__ __launch_bounds__(128)
void agg_kernel(const float* __restrict__ features,
                const float* __restrict__ output_pts,
                const int*   __restrict__ indices,
                const float* __restrict__ l2_w, const float* __restrict__ l2_b,
                const float* __restrict__ l3_w, const float* __restrict__ l3_b)
{
    __shared__ __align__(16) float  sA1[96];
    __shared__ __align__(16) float  sC1[32];
    __shared__ __align__(16) __half sH1[4][32*PH1];
    __shared__ __align__(16) __half sH2[4][32*PH2];
    __shared__ __align__(8)  float  sD [4][32*PDD];
    __shared__ int sI[4][2][KNB];

    const int tid = threadIdx.x;
    if (tid < 96)  sA1[tid] = g_A1[tid];
    if (tid < 32)  sC1[tid] = g_c1[tid];
    __syncthreads();

    const int w     = tid >> 5;
    const int lane  = tid & 31;
    const int g     = lane >> 2;
    const int t4    = lane & 3;
    const int q     = lane >> 4;
    const int k     = lane & 15;
    const int pbase = blockIdx.x * 8 + w * 2;
    const int b     = pbase >> 13;
    const float* __restrict__ fb = features + (size_t)b * NN * CIN;

    const int a_r  = (lane & 7) + ((lane >> 3) & 1) * 8;
    const int a_ka = lane >> 4;

    // ---- one-time: W2/W3/bias B-fragments in registers ----
    uint32_t b2[2][2][2], b3[2][2];
    float bs2[2][2], bs3[2][2];
    {
        const int n0 = g, k0 = 2*t4;
        #pragma unroll
        for (int nt = 0; nt < 2; nt++) {
            const int n = nt*8 + n0;
            #pragma unroll
            for (int kc = 0; kc < 2; kc++) {
                b2[kc][nt][0] = packh2(l2_w[n*32 + kc*16 + k0    ], l2_w[n*32 + kc*16 + k0 + 1]);
                b2[kc][nt][1] = packh2(l2_w[n*32 + kc*16 + k0 + 8], l2_w[n*32 + kc*16 + k0 + 9]);
            }
            b3[nt][0] = packh2(l3_w[n*16 + k0    ], l3_w[n*16 + k0 + 1]);
            b3[nt][1] = packh2(l3_w[n*16 + k0 + 8], l3_w[n*16 + k0 + 9]);
            bs2[nt][0] = l2_b[nt*8 + k0];  bs2[nt][1] = l2_b[nt*8 + k0 + 1];
            bs3[nt][0] = l3_b[nt*8 + k0];  bs3[nt][1] = l3_b[nt*8 + k0 + 1];
        }
    }

    __half* H1 = sH1[w];
    __half* H2 = sH2[w];
    float*  Dd = sD[w];
    const uint32_t h1b = smem_u32(H1);
    const uint32_t h2b = smem_u32(H2);

    // ---- layer 1 (FFMA) ----
    {
        const int p   = pbase + q;
        const int idx = indices[p*KNB + k];
        sI[w][q][k] = idx;
        const float ox = output_pts[p*3+0];
        const float oy = output_pts[p*3+1];
        const float oz = output_pts[p*3+2];
        const float4 P = g_pts4[b*NN + idx];
        const float rx = P.x - ox, ry = P.y - oy, rz = P.z - oz;

        #pragma unroll
        for (int i = 0; i < 8; i++) {
            float v0 = fmaxf(sC1[4*i+0] + sA1[(4*i+0)*3]*rx + sA1[(4*i+0)*3+1]*ry + sA1[(4*i+0)*3+2]*rz, 0.f);
            float v1 = fmaxf(sC1[4*i+1] + sA1[(4*i+1)*3]*rx + sA1[(4*i+1)*3+1]*ry + sA1[(4*i+1)*3+2]*rz, 0.f);
            float v2 = fmaxf(sC1[4*i+2] + sA1[(4*i+2)*3]*rx + sA1[(4*i+2)*3+1]*ry + sA1[(4*i+2)*3+2]*rz, 0.f);
            float v3 = fmaxf(sC1[4*i+3] + sA1[(4*i+3)*3]*rx + sA1[(4*i+3)*3+1]*ry + sA1[(4*i+3)*3+2]*rz, 0.f);
            uint2 pk = make_uint2(packh2(v0, v1), packh2(v2, v3));
            *(uint2*)&H1[lane*PH1 + 4*i] = pk;
        }
    }
    __syncwarp();

    // ---- hoisted phase-3 A-fragment gather ----
    uint32_t afr[2][4][4];
    #pragma unroll
    for (int qq = 0; qq < 2; qq++) {
        const float* rA = fb + (size_t)sI[w][qq][2*t4    ] * CIN;
        const float* rB = fb + (size_t)sI[w][qq][2*t4 + 1] * CIN;
        const float* rC = fb + (size_t)sI[w][qq][2*t4 + 8] * CIN;
        const float* rD = fb + (size_t)sI[w][qq][2*t4 + 9] * CIN;
        #pragma unroll
        for (int mt = 0; mt < 4; mt++) {
            const int c0 = mt*16 + g, c1 = mt*16 + g + 8;
            afr[qq][mt][0] = packh2(rA[c0], rB[c0]);
            afr[qq][mt][1] = packh2(rA[c1], rB[c1]);
            afr[qq][mt][2] = packh2(rC[c0], rD[c0]);
            afr[qq][mt][3] = packh2(rC[c1], rD[c1]);
        }
    }

    // ---- layer 2 ----
    {
        float acc2[2][2][4];
        #pragma unroll
        for (int mt = 0; mt < 2; mt++)
            #pragma unroll
            for (int nt = 0; nt < 2; nt++)
                #pragma unroll
                for (int i = 0; i < 4; i++) acc2[mt][nt][i] = 0.f;

        #pragma unroll
        for (int kc = 0; kc < 2; kc++) {
            uint32_t a[2][4];
            #pragma unroll
            for (int mt = 0; mt < 2; mt++) {
                uint32_t addr = h1b + (uint32_t)((mt*16 + a_r)*PH1 + kc*16 + a_ka*8) * 2;
                ldsm_x4(a[mt][0], a[mt][1], a[mt][2], a[mt][3], addr);
            }
            #pragma unroll
            for (int mt = 0; mt < 2; mt++)
                #pragma unroll
                for (int nt = 0; nt < 2; nt++)
                    mma_f16(acc2[mt][nt], a[mt], b2[kc][nt]);
        }
        #pragma unroll
        for (int mt = 0; mt < 2; mt++)
            #pragma unroll
            for (int nt = 0; nt < 2; nt++) {
                const int col = nt*8 + 2*t4;
                *(uint32_t*)&H2[(mt*16 + g    )*PH2 + col] =
                    packh2(fmaxf(acc2[mt][nt][0] + bs2[nt][0], 0.f),
                           fmaxf(acc2[mt][nt][1] + bs2[nt][1], 0.f));
                *(uint32_t*)&H2[(mt*16 + g + 8)*PH2 + col] =
                    packh2(fmaxf(acc2[mt][nt][2] + bs2[nt][0], 0.f),
                           fmaxf(acc2[mt][nt][3] + bs2[nt][1], 0.f));
            }
    }
    __syncwarp();

    // ---- layer 3 ----
    {
        float acc3[2][2][4];
        #pragma unroll
        for (int mt = 0; mt < 2; mt++)
            #pragma unroll
            for (int nt = 0; nt < 2; nt++)
                #pragma unroll
                for (int i = 0; i < 4; i++) acc3[mt][nt][i] = 0.f;

        uint32_t a[2][4];
        #pragma unroll
        for (int mt = 0; mt < 2; mt++) {
            uint32_t addr = h2b + (uint32_t)((mt*16 + a_r)*PH2 + a_ka*8) * 2;
            ldsm_x4(a[mt][0], a[mt][1], a[mt][2], a[mt][3], addr);
        }
        #pragma unroll
        for (int mt = 0; mt < 2; mt++)
            #pragma unroll
            for (int nt = 0; nt < 2; nt++)
                mma_f16(acc3[mt][nt], a[mt], b3[nt]);

        #pragma unroll
        for (int mt = 0; mt < 2; mt++)
            #pragma unroll
            for (int nt = 0; nt < 2; nt++) {
                const int col = nt*8 + 2*t4;
                float2 v0 = make_float2(fmaxf(acc3[mt][nt][0] + bs3[nt][0], 0.f),
                                        fmaxf(acc3[mt][nt][1] + bs3[nt][1], 0.f));
                float2 v1 = make_float2(fmaxf(acc3[mt][nt][2] + bs3[nt][0], 0.f),
                                        fmaxf(acc3[mt][nt][3] + bs3[nt][1], 0.f));
                *(float2*)&Dd[(mt*16 + g    )*PDD + col] = v0;
                *(float2*)&Dd[(mt*16 + g + 8)*PDD + col] = v1;
            }
    }
    __syncwarp();

    // ---- phase 3: fp16 k16 mma; chunk-major pre-swizzled stores ----
    #pragma unroll
    for (int qq = 0; qq < 2; qq++) {
        uint32_t bfr[2][2];
        #pragma unroll
        for (int nt = 0; nt < 2; nt++) {
            const int n = nt*8 + g;
            bfr[nt][0] = packh2(Dd[(qq*16 + 2*t4    )*PDD + n],
                                Dd[(qq*16 + 2*t4 + 1)*PDD + n]);
            bfr[nt][1] = packh2(Dd[(qq*16 + 2*t4 + 8)*PDD + n],
                                Dd[(qq*16 + 2*t4 + 9)*PDD + n]);
        }

        float acc[4][2][4];
        #pragma unroll
        for (int mt = 0; mt < 4; mt++)
            #pragma unroll
            for (int nt = 0; nt < 2; nt++)
                #pragma unroll
                for (int i = 0; i < 4; i++) acc[mt][nt][i] = 0.f;

        #pragma unroll
        for (int mt = 0; mt < 4; mt++) {
            mma_f16(acc[mt][0], afr[qq][mt], bfr[0]);
            mma_f16(acc[mt][1], afr[qq][mt], bfr[1]);
        }

        const int p  = pbase + qq;
        const int rl = p & 127;
        uint32_t o = ((uint32_t)rl << 7) + ((uint32_t)lane << 2);
        o = SWZ(o);
        char* tbase = (char*)g_aggc + (size_t)(p & ~127) * 128 + o;
        const size_t cstride = (size_t)NPTS * 128;   // bytes per chunk
        #pragma unroll
        for (int mt = 0; mt < 4; mt++) {
            #pragma unroll
            for (int nt = 0; nt < 2; nt++) {
                const int q0 = (mt*2 + 0)*2 + nt;
                const int q1 = (mt*2 + 1)*2 + nt;
                *(uint32_t*)(tbase + (size_t)q0*cstride) = packh2(acc[mt][nt][0], acc[mt][nt][1]);
                *(uint32_t*)(tbase + (size_t)q1*cstride) = packh2(acc[mt][nt][2], acc[mt][nt][3]);
            }
        }
    }
}

// ============================================================
// Kernel B: fp16 mma GEMM with cp.async.bulk tile loads.
// 256 thr, 8 warps (2x4, warp 64x32), 3-stage mbarrier pipeline,
// 2 bulk copies (16KB A + 16KB B) per 64-half K-chunk.
// ============================================================
#define STGB   32768                 // bytes per stage (A 16K + B 16K)
#define NCH    16
#define MB_OFF (3*STGB)
#define GEMM_SMEM (MB_OFF + 64 + 512)

__global__ __launch_bounds__(256)
void gemm_mma_kernel(const float* __restrict__ bias,
                     const float* __restrict__ output_pts,
                     float* __restrict__ out)
{
    extern __shared__ __align__(1024) char smem[];
    float* sbias = (float*)(smem + MB_OFF + 64);

    const int tid  = threadIdx.x;
    const int lane = tid & 31;
    const int warp = tid >> 5;
    const int g    = lane >> 2;
    const int t4   = lane & 3;
    const int m0   = (warp >> 2) * 64;
    const int n0   = (warp & 3) * 32;
    const int p0   = blockIdx.x * 128;

    const uint32_t smb = smem_u32(smem);
    const uint32_t mb  = smb + MB_OFF;

    if (tid == 0) {
        MBAR_INIT(mb + 0, 1);
        MBAR_INIT(mb + 8, 1);
        MBAR_INIT(mb + 16, 1);
    }
    if (tid < COUT) sbias[tid] = bias[tid];
    __syncthreads();

    auto issue = [&](int kc, int st) {
        MBAR_EXPECT_TX(mb + 8*st, 32768);
        CP_BULK(smb + st*STGB,
                (const char*)g_aggc + (size_t)kc*(size_t)NPTS*128 + (size_t)p0*128,
                16384, mb + 8*st);
        CP_BULK(smb + st*STGB + 16384,
                (const char*)g_WpTh + (size_t)kc*COUT*128,
                16384, mb + 8*st);
    };
    if (tid == 0) { issue(0, 0); issue(1, 1); issue(2, 2); }

    const int a_r  = (lane & 7) + ((lane >> 3) & 1) * 8;
    const int a_ka = lane >> 4;
    const int b_r  = (lane & 7) + (lane >> 4) * 8;
    const int b_ka = (lane >> 3) & 1;

    float acc[4][4][4];
    #pragma unroll
    for (int mf = 0; mf < 4; mf++)
        #pragma unroll
        for (int nf = 0; nf < 4; nf++)
            #pragma unroll
            for (int i = 0; i < 4; i++) acc[mf][nf][i] = 0.f;

    for (int kc = 0; kc < NCH; kc++) {
        const int st = kc % 3;
        MBAR_WAIT(mb + 8*st, (kc / 3) & 1);

        const uint32_t sa = smb + st*STGB;
        const uint32_t sb = sa + 16384;

        #pragma unroll 4
        for (int ks = 0; ks < 4; ks++) {
            uint32_t a[4][4], bb[4][2];
            #pragma unroll
            for (int mf = 0; mf < 4; mf++) {
                uint32_t o = (uint32_t)(m0 + mf*16 + a_r)*128 + ks*32 + a_ka*16;
                ldsm_x4(a[mf][0], a[mf][1], a[mf][2], a[mf][3], sa + SWZ(o));
            }
            #pragma unroll
            for (int np = 0; np < 2; np++) {
                uint32_t o = (uint32_t)(n0 + np*16 + b_r)*128 + ks*32 + b_ka*16;
                ldsm_x4(bb[np*2][0], bb[np*2][1], bb[np*2+1][0], bb[np*2+1][1], sb + SWZ(o));
            }
            #pragma unroll
            for (int mf = 0; mf < 4; mf++)
                #pragma unroll
                for (int nf = 0; nf < 4; nf++)
                    mma_f16(acc[mf][nf], a[mf], bb[nf]);
        }

        __syncthreads();
        if (tid == 0 && kc + 3 < NCH) issue(kc + 3, st);
    }

    const float inv_k = 1.0f / (float)KNB;
    #pragma unroll
    for (int mf = 0; mf < 4; mf++) {
        const int row = p0 + m0 + mf*16 + g;
        #pragma unroll
        for (int nf = 0; nf < 4; nf++) {
            const int col = n0 + nf*8 + t4*2;
            const float b0 = sbias[col], b1 = sbias[col+1];
            float2 v0 = make_float2(acc[mf][nf][0]*inv_k + b0, acc[mf][nf][1]*inv_k + b1);
            float2 v1 = make_float2(acc[mf][nf][2]*inv_k + b0, acc[mf][nf][3]*inv_k + b1);
            *(float2*)(out + (size_t)row*COUT + col)     = v0;
            *(float2*)(out + (size_t)(row+8)*COUT + col) = v1;
        }
    }

    // fused output_pts passthrough: 49152 float4 over 512 CTAs = 96 each
    {
        const float4* src = (const float4*)output_pts;
        float4* dst = (float4*)(out + (size_t)NPTS*COUT);
        const int base = blockIdx.x * 96;
        if (tid < 96) dst[base + tid] = src[base + tid];
    }
}

// ============================================================
extern "C" void kernel_launch(void* const* d_in, const int* in_sizes, int n_in,
                              void* d_out, int out_size)
{
    const float* features   = (const float*)d_in[0];
    const float* input_pts  = (const float*)d_in[1];
    const float* output_pts = (const float*)d_in[2];
    const int*   indices    = (const int*)  d_in[3];
    const float* centers    = (const float*)d_in[4];
    const float* weight     = (const float*)d_in[5];
    const float* bias       = (const float*)d_in[6];
    const float* l1_w       = (const float*)d_in[7];
    const float* l1_b       = (const float*)d_in[8];
    const float* l2_w       = (const float*)d_in[9];
    const float* l2_b       = (const float*)d_in[10];
    const float* l3_w       = (const float*)d_in[11];
    const float* l3_b       = (const float*)d_in[12];

    float* out = (float*)d_out;

    cudaFuncSetAttribute(gemm_mma_kernel,
                         cudaFuncAttributeMaxDynamicSharedMemorySize, GEMM_SMEM);

    prep_kernel<<<(AGGK*COUT + 255)/256, 256>>>(weight, input_pts, l1_w, l1_b, centers);
    agg_kernel<<<NPTS/8, 128>>>(features, output_pts, indices,
                                l2_w, l2_b, l3_w, l3_b);
    gemm_mma_kernel<<<NPTS/128, 256, GEMM_SMEM>>>(bias, output_pts, out);
}

// round 15
// speedup vs baseline: 1.3707x; 1.3707x over previous
#include <cuda_runtime.h>
#include <cuda_bf16.h>
#include <cuda_fp16.h>
#include <cstdint>

// Problem constants
#define NB   8
#define NN   8192
#define CIN  64
#define COUT 128
#define KNB  16
#define MM   16
#define NPTS (NB*NN)            // 65536
#define AGGK (CIN*MM)           // 1024

// -------- device scratch --------
__device__ __half g_aggh[(size_t)NPTS * AGGK];   // 134 MB, [p][j], fp16
__device__ __half g_WpTh[(size_t)COUT * AGGK];   // weight^T [n][j], fp16
__device__ __half g_fh[(size_t)NPTS * CIN];      // fp16 features, 8 MB
__device__ float4 g_pts4[NPTS];                  // padded input_pts, 1 MB
__device__ float  g_A1[32*3];
__device__ float  g_c1[32];

// j bijection: c = mt*16 + ih*8 + g ; m = nt*8 + t4*2 + b
// u = ((mt*2+ih)*2 + nt)*32 + g*4 + t4 ; j = 2u + b

// ============================================================
// PTX helpers
// ============================================================
__device__ __forceinline__ uint32_t smem_u32(const void* p) {
    uint32_t a;
    asm("{ .reg .u64 t; cvta.to.shared.u64 t, %1; cvt.u32.u64 %0, t; }" : "=r"(a) : "l"(p));
    return a;
}
__device__ __forceinline__ uint32_t packh2(float a, float b) {
    __half2 h = __floats2half2_rn(a, b);
    return *(uint32_t*)&h;
}
__device__ __forceinline__ uint32_t pack2h(__half a, __half b) {
    __half2 h = __halves2half2(a, b);
    return *(uint32_t*)&h;
}
#define CP_ASYNC16(dst, src) \
    asm volatile("cp.async.cg.shared.global [%0], [%1], 16;" :: "r"(dst), "l"(src) : "memory")
#define CP_COMMIT() asm volatile("cp.async.commit_group;" ::: "memory")
#define CP_WAIT1()  asm volatile("cp.async.wait_group 1;" ::: "memory")
#define CP_WAIT0()  asm volatile("cp.async.wait_group 0;" ::: "memory")

__device__ __forceinline__ void ldsm_x4(uint32_t& r0, uint32_t& r1, uint32_t& r2, uint32_t& r3,
                                        uint32_t addr) {
    asm volatile("ldmatrix.sync.aligned.m8n8.x4.shared.b16 {%0,%1,%2,%3}, [%4];"
                 : "=r"(r0), "=r"(r1), "=r"(r2), "=r"(r3) : "r"(addr));
}
__device__ __forceinline__ void mma_f16(float c[4], const uint32_t a[4], const uint32_t b[2]) {
    asm volatile(
        "mma.sync.aligned.m16n8k16.row.col.f32.f16.f16.f32 "
        "{%0,%1,%2,%3}, {%4,%5,%6,%7}, {%8,%9}, {%0,%1,%2,%3};"
        : "+f"(c[0]), "+f"(c[1]), "+f"(c[2]), "+f"(c[3])
        : "r"(a[0]), "r"(a[1]), "r"(a[2]), "r"(a[3]), "r"(b[0]), "r"(b[1]));
}

// ============================================================
// Prep (fused): weight permute + feature fp16 convert + pts4 pack
// + (block 0) layer-1 affine collapse.
// ============================================================
__global__ void prep_kernel(const float* __restrict__ weight,
                            const float* __restrict__ features,
                            const float* __restrict__ input_pts,
                            const float* __restrict__ l1_w,
                            const float* __restrict__ l1_b,
                            const float* __restrict__ centers)
{
    int e = blockIdx.x * blockDim.x + threadIdx.x;   // 0 .. 131071

    // weight -> g_WpTh[n*1024 + j(c,m)], fp16
    if (e < AGGK * COUT) {
        int n  = e & 127;
        int cm = e >> 7;
        int m  = cm & 15;
        int c  = cm >> 4;
        int gg = c & 7, ih = (c >> 3) & 1, mt = c >> 4;
        int nt = m >> 3, t4 = (m >> 1) & 3, b = m & 1;
        int u  = ((mt*2 + ih)*2 + nt)*32 + gg*4 + t4;
        g_WpTh[(size_t)n*AGGK + 2*u + b] = __float2half_rn(weight[e]);
    }

    // features fp32 -> fp16 (grid-stride over half2 units)
    {
        const float2* fsrc = (const float2*)features;
        __half2* fdst = (__half2*)g_fh;
        const int total = NPTS * CIN / 2;            // 2,097,152
        for (int i = e; i < total; i += 131072)
            fdst[i] = __float22half2_rn(fsrc[i]);
    }

    // input_pts [p][3] -> g_pts4[p]
    if (e < NPTS) {
        g_pts4[e] = make_float4(input_pts[e*3+0], input_pts[e*3+1],
                                input_pts[e*3+2], 0.f);
    }

    // layer-1 affine collapse (block 0, lanes 0..31)
    if (blockIdx.x == 0 && threadIdx.x < 32) {
        int o = threadIdx.x;
        float a0 = 0.f, a1 = 0.f, a2 = 0.f;
        float c = l1_b[o];
        #pragma unroll
        for (int m = 0; m < MM; m++) {
            float w0 = l1_w[o*48 + 0*16 + m];
            float w1 = l1_w[o*48 + 1*16 + m];
            float w2 = l1_w[o*48 + 2*16 + m];
            a0 += w0; a1 += w1; a2 += w2;
            c -= w0 * centers[0*16 + m];
            c -= w1 * centers[1*16 + m];
            c -= w2 * centers[2*16 + m];
        }
        g_A1[o*3+0] = a0; g_A1[o*3+1] = a1; g_A1[o*3+2] = a2;
        g_c1[o] = c;
    }
}

// ============================================================
// Kernel A (v8 = R13 + fp16 feature gather).
// ============================================================
#define PH1 40   // halves
#define PH2 24   // halves
#define PDD 20   // floats

__global__ __launch_bounds__(128)
void agg_kernel(const float* __restrict__ output_pts,
                const int*   __restrict__ indices,
                const float* __restrict__ l2_w, const float* __restrict__ l2_b,
                const float* __restrict__ l3_w, const float* __restrict__ l3_b)
{
    __shared__ __align__(16) float  sA1[96];
    __shared__ __align__(16) float  sC1[32];
    __shared__ __align__(16) __half sH1[4][32*PH1];
    __shared__ __align__(16) __half sH2[4][32*PH2];
    __shared__ __align__(8)  float  sD [4][32*PDD];
    __shared__ int sI[4][2][KNB];

    const int tid = threadIdx.x;
    if (tid < 96)  sA1[tid] = g_A1[tid];
    if (tid < 32)  sC1[tid] = g_c1[tid];
    __syncthreads();

    const int w     = tid >> 5;
    const int lane  = tid & 31;
    const int g     = lane >> 2;
    const int t4    = lane & 3;
    const int q     = lane >> 4;
    const int k     = lane & 15;
    const int pbase = blockIdx.x * 8 + w * 2;
    const int b     = pbase >> 13;
    const __half* __restrict__ fh = g_fh + (size_t)b * NN * CIN;

    const int a_r  = (lane & 7) + ((lane >> 3) & 1) * 8;
    const int a_ka = lane >> 4;

    // ---- one-time: W2/W3/bias B-fragments in registers ----
    uint32_t b2[2][2][2], b3[2][2];
    float bs2[2][2], bs3[2][2];
    {
        const int n0 = g, k0 = 2*t4;
        #pragma unroll
        for (int nt = 0; nt < 2; nt++) {
            const int n = nt*8 + n0;
            #pragma unroll
            for (int kc = 0; kc < 2; kc++) {
                b2[kc][nt][0] = packh2(l2_w[n*32 + kc*16 + k0    ], l2_w[n*32 + kc*16 + k0 + 1]);
                b2[kc][nt][1] = packh2(l2_w[n*32 + kc*16 + k0 + 8], l2_w[n*32 + kc*16 + k0 + 9]);
            }
            b3[nt][0] = packh2(l3_w[n*16 + k0    ], l3_w[n*16 + k0 + 1]);
            b3[nt][1] = packh2(l3_w[n*16 + k0 + 8], l3_w[n*16 + k0 + 9]);
            bs2[nt][0] = l2_b[nt*8 + k0];  bs2[nt][1] = l2_b[nt*8 + k0 + 1];
            bs3[nt][0] = l3_b[nt*8 + k0];  bs3[nt][1] = l3_b[nt*8 + k0 + 1];
        }
    }

    __half* H1 = sH1[w];
    __half* H2 = sH2[w];
    float*  Dd = sD[w];
    const uint32_t h1b = smem_u32(H1);
    const uint32_t h2b = smem_u32(H2);

    // ---- layer 1 (FFMA): sample = lane; single float4 point gather ----
    {
        const int p   = pbase + q;
        const int idx = indices[p*KNB + k];
        sI[w][q][k] = idx;
        const float ox = output_pts[p*3+0];
        const float oy = output_pts[p*3+1];
        const float oz = output_pts[p*3+2];
        const float4 P = g_pts4[b*NN + idx];
        const float rx = P.x - ox, ry = P.y - oy, rz = P.z - oz;

        #pragma unroll
        for (int i = 0; i < 8; i++) {
            float v0 = fmaxf(sC1[4*i+0] + sA1[(4*i+0)*3]*rx + sA1[(4*i+0)*3+1]*ry + sA1[(4*i+0)*3+2]*rz, 0.f);
            float v1 = fmaxf(sC1[4*i+1] + sA1[(4*i+1)*3]*rx + sA1[(4*i+1)*3+1]*ry + sA1[(4*i+1)*3+2]*rz, 0.f);
            float v2 = fmaxf(sC1[4*i+2] + sA1[(4*i+2)*3]*rx + sA1[(4*i+2)*3+1]*ry + sA1[(4*i+2)*3+2]*rz, 0.f);
            float v3 = fmaxf(sC1[4*i+3] + sA1[(4*i+3)*3]*rx + sA1[(4*i+3)*3+1]*ry + sA1[(4*i+3)*3+2]*rz, 0.f);
            uint2 pk = make_uint2(packh2(v0, v1), packh2(v2, v3));
            *(uint2*)&H1[lane*PH1 + 4*i] = pk;
        }
    }
    __syncwarp();

    // ---- hoisted phase-3 A-fragment gather (fp16 rows, paired sectors) ----
    uint32_t afr[2][4][4];
    #pragma unroll
    for (int qq = 0; qq < 2; qq++) {
        const __half* rA = fh + (size_t)sI[w][qq][2*t4    ] * CIN;
        const __half* rB = fh + (size_t)sI[w][qq][2*t4 + 1] * CIN;
        const __half* rC = fh + (size_t)sI[w][qq][2*t4 + 8] * CIN;
        const __half* rD = fh + (size_t)sI[w][qq][2*t4 + 9] * CIN;
        #pragma unroll
        for (int mt = 0; mt < 4; mt++) {
            const int c0 = mt*16 + g, c1 = mt*16 + g + 8;
            afr[qq][mt][0] = pack2h(rA[c0], rB[c0]);
            afr[qq][mt][1] = pack2h(rA[c1], rB[c1]);
            afr[qq][mt][2] = pack2h(rC[c0], rD[c0]);
            afr[qq][mt][3] = pack2h(rC[c1], rD[c1]);
        }
    }

    // ---- layer 2: H2[32,16] = relu(H1[32,32] @ W2^T + b2), fp16 mma ----
    {
        float acc2[2][2][4];
        #pragma unroll
        for (int mt = 0; mt < 2; mt++)
            #pragma unroll
            for (int nt = 0; nt < 2; nt++)
                #pragma unroll
                for (int i = 0; i < 4; i++) acc2[mt][nt][i] = 0.f;

        #pragma unroll
        for (int kc = 0; kc < 2; kc++) {
            uint32_t a[2][4];
            #pragma unroll
            for (int mt = 0; mt < 2; mt++) {
                uint32_t addr = h1b + (uint32_t)((mt*16 + a_r)*PH1 + kc*16 + a_ka*8) * 2;
                ldsm_x4(a[mt][0], a[mt][1], a[mt][2], a[mt][3], addr);
            }
            #pragma unroll
            for (int mt = 0; mt < 2; mt++)
                #pragma unroll
                for (int nt = 0; nt < 2; nt++)
                    mma_f16(acc2[mt][nt], a[mt], b2[kc][nt]);
        }
        #pragma unroll
        for (int mt = 0; mt < 2; mt++)
            #pragma unroll
            for (int nt = 0; nt < 2; nt++) {
                const int col = nt*8 + 2*t4;
                *(uint32_t*)&H2[(mt*16 + g    )*PH2 + col] =
                    packh2(fmaxf(acc2[mt][nt][0] + bs2[nt][0], 0.f),
                           fmaxf(acc2[mt][nt][1] + bs2[nt][1], 0.f));
                *(uint32_t*)&H2[(mt*16 + g + 8)*PH2 + col] =
                    packh2(fmaxf(acc2[mt][nt][2] + bs2[nt][0], 0.f),
                           fmaxf(acc2[mt][nt][3] + bs2[nt][1], 0.f));
            }
    }
    __syncwarp();

    // ---- layer 3: D[32,16] = relu(H2[32,16] @ W3^T + b3), fp16 mma ----
    {
        float acc3[2][2][4];
        #pragma unroll
        for (int mt = 0; mt < 2; mt++)
            #pragma unroll
            for (int nt = 0; nt < 2; nt++)
                #pragma unroll
                for (int i = 0; i < 4; i++) acc3[mt][nt][i] = 0.f;

        uint32_t a[2][4];
        #pragma unroll
        for (int mt = 0; mt < 2; mt++) {
            uint32_t addr = h2b + (uint32_t)((mt*16 + a_r)*PH2 + a_ka*8) * 2;
            ldsm_x4(a[mt][0], a[mt][1], a[mt][2], a[mt][3], addr);
        }
        #pragma unroll
        for (int mt = 0; mt < 2; mt++)
            #pragma unroll
            for (int nt = 0; nt < 2; nt++)
                mma_f16(acc3[mt][nt], a[mt], b3[nt]);

        #pragma unroll
        for (int mt = 0; mt < 2; mt++)
            #pragma unroll
            for (int nt = 0; nt < 2; nt++) {
                const int col = nt*8 + 2*t4;
                float2 v0 = make_float2(fmaxf(acc3[mt][nt][0] + bs3[nt][0], 0.f),
                                        fmaxf(acc3[mt][nt][1] + bs3[nt][1], 0.f));
                float2 v1 = make_float2(fmaxf(acc3[mt][nt][2] + bs3[nt][0], 0.f),
                                        fmaxf(acc3[mt][nt][3] + bs3[nt][1], 0.f));
                *(float2*)&Dd[(mt*16 + g    )*PDD + col] = v0;
                *(float2*)&Dd[(mt*16 + g + 8)*PDD + col] = v1;
            }
    }
    __syncwarp();

    // ---- phase 3: S = F^T(64x16) @ D(16x16) per point, fp16 k16 mma ----
    #pragma unroll
    for (int qq = 0; qq < 2; qq++) {
        uint32_t bfr[2][2];
        #pragma unroll
        for (int nt = 0; nt < 2; nt++) {
            const int n = nt*8 + g;
            bfr[nt][0] = packh2(Dd[(qq*16 + 2*t4    )*PDD + n],
                                Dd[(qq*16 + 2*t4 + 1)*PDD + n]);
            bfr[nt][1] = packh2(Dd[(qq*16 + 2*t4 + 8)*PDD + n],
                                Dd[(qq*16 + 2*t4 + 9)*PDD + n]);
        }

        float acc[4][2][4];
        #pragma unroll
        for (int mt = 0; mt < 4; mt++)
            #pragma unroll
            for (int nt = 0; nt < 2; nt++)
                #pragma unroll
                for (int i = 0; i < 4; i++) acc[mt][nt][i] = 0.f;

        #pragma unroll
        for (int mt = 0; mt < 4; mt++) {
            mma_f16(acc[mt][0], afr[qq][mt], bfr[0]);
            mma_f16(acc[mt][1], afr[qq][mt], bfr[1]);
        }

        __half2* orow = (__half2*)(g_aggh + (size_t)(pbase + qq) * AGGK);
        #pragma unroll
        for (int mt = 0; mt < 4; mt++) {
            #pragma unroll
            for (int nt = 0; nt < 2; nt++) {
                const int u0 = ((mt*2 + 0)*2 + nt)*32 + lane;
                const int u1 = ((mt*2 + 1)*2 + nt)*32 + lane;
                orow[u0] = __floats2half2_rn(acc[mt][nt][0], acc[mt][nt][1]);
                orow[u1] = __floats2half2_rn(acc[mt][nt][2], acc[mt][nt][3]);
            }
        }
    }
}

// ============================================================
// Kernel B: fp16 mma GEMM (R6/R13 config) + fused output_pts copy.
// ============================================================
#define GBK    64
#define HPITCH 72
#define HTSZ   (128*HPITCH*2)       // 18432 B
#define GSTG   3
#define NCH    (AGGK/GBK)           // 16
#define GEMM_SMEM (GSTG*2*HTSZ + 512)

__global__ __launch_bounds__(256)
void gemm_mma_kernel(const float* __restrict__ bias,
                     const float* __restrict__ output_pts,
                     float* __restrict__ out)
{
    extern __shared__ __align__(16) char smem[];
    float* sbias = (float*)(smem + GSTG*2*HTSZ);

    const int tid  = threadIdx.x;
    const int lane = tid & 31;
    const int warp = tid >> 5;
    const int g    = lane >> 2;
    const int t4   = lane & 3;
    const int m0   = (warp >> 2) * 64;
    const int n0   = (warp & 3) * 32;
    const int p0   = blockIdx.x * 128;

    if (tid < COUT) sbias[tid] = bias[tid];

    const uint32_t smb = smem_u32(smem);
    const __half* gA = g_aggh + (size_t)p0 * AGGK;
    const __half* gB = g_WpTh;

    auto load_chunk = [&](int kc, int st) {
        const uint32_t sa = smb + st*2*HTSZ;
        const uint32_t sb = sa + HTSZ;
        #pragma unroll
        for (int i = 0; i < 4; i++) {
            const int a   = tid + i*256;
            const int row = a >> 3;
            const int ca  = a & 7;
            const uint32_t doff = (uint32_t)(row*HPITCH + ca*8) * 2;
            CP_ASYNC16(sa + doff, gA + (size_t)row*AGGK + kc*GBK + ca*8);
            CP_ASYNC16(sb + doff, gB + (size_t)row*AGGK + kc*GBK + ca*8);
        }
    };

    const int a_r  = (lane & 7) + ((lane >> 3) & 1) * 8;
    const int a_ka = lane >> 4;
    const int b_r  = (lane & 7) + (lane >> 4) * 8;
    const int b_ka = (lane >> 3) & 1;

    float acc[4][4][4];
    #pragma unroll
    for (int mf = 0; mf < 4; mf++)
        #pragma unroll
        for (int nf = 0; nf < 4; nf++)
            #pragma unroll
            for (int i = 0; i < 4; i++) acc[mf][nf][i] = 0.f;

    load_chunk(0, 0); CP_COMMIT();
    load_chunk(1, 1); CP_COMMIT();

    for (int kc = 0; kc < NCH; kc++) {
        const int st = kc % GSTG;
        CP_WAIT1();
        __syncthreads();

        const uint32_t sa = smb + st*2*HTSZ;
        const uint32_t sb = sa + HTSZ;

        #pragma unroll 4
        for (int ks = 0; ks < 4; ks++) {
            uint32_t a[4][4], bb[4][2];
            #pragma unroll
            for (int mf = 0; mf < 4; mf++) {
                uint32_t addr = sa + (uint32_t)((m0 + mf*16 + a_r)*HPITCH
                                + (ks*2 + a_ka)*8) * 2;
                ldsm_x4(a[mf][0], a[mf][1], a[mf][2], a[mf][3], addr);
            }
            #pragma unroll
            for (int np = 0; np < 2; np++) {
                uint32_t addr = sb + (uint32_t)((n0 + np*16 + b_r)*HPITCH
                                + (ks*2 + b_ka)*8) * 2;
                ldsm_x4(bb[np*2][0], bb[np*2][1], bb[np*2+1][0], bb[np*2+1][1], addr);
            }
            #pragma unroll
            for (int mf = 0; mf < 4; mf++)
                #pragma unroll
                for (int nf = 0; nf < 4; nf++)
                    mma_f16(acc[mf][nf], a[mf], bb[nf]);
        }

        if (kc + 2 < NCH) load_chunk(kc + 2, (kc + 2) % GSTG);
        CP_COMMIT();
    }

    const float inv_k = 1.0f / (float)KNB;
    #pragma unroll
    for (int mf = 0; mf < 4; mf++) {
        const int row = p0 + m0 + mf*16 + g;
        #pragma unroll
        for (int nf = 0; nf < 4; nf++) {
            const int col = n0 + nf*8 + t4*2;
            const float b0 = sbias[col], b1 = sbias[col+1];
            float2 v0 = make_float2(acc[mf][nf][0]*inv_k + b0, acc[mf][nf][1]*inv_k + b1);
            float2 v1 = make_float2(acc[mf][nf][2]*inv_k + b0, acc[mf][nf][3]*inv_k + b1);
            *(float2*)(out + (size_t)row*COUT + col)     = v0;
            *(float2*)(out + (size_t)(row+8)*COUT + col) = v1;
        }
    }

    // fused output_pts passthrough: 49152 float4 over 512 CTAs = 96 each
    {
        const float4* src = (const float4*)output_pts;
        float4* dst = (float4*)(out + (size_t)NPTS*COUT);
        const int base = blockIdx.x * 96;
        if (tid < 96) dst[base + tid] = src[base + tid];
    }
}

// ============================================================
extern "C" void kernel_launch(void* const* d_in, const int* in_sizes, int n_in,
                              void* d_out, int out_size)
{
    const float* features   = (const float*)d_in[0];
    const float* input_pts  = (const float*)d_in[1];
    const float* output_pts = (const float*)d_in[2];
    const int*   indices    = (const int*)  d_in[3];
    const float* centers    = (const float*)d_in[4];
    const float* weight     = (const float*)d_in[5];
    const float* bias       = (const float*)d_in[6];
    const float* l1_w       = (const float*)d_in[7];
    const float* l1_b       = (const float*)d_in[8];
    const float* l2_w       = (const float*)d_in[9];
    const float* l2_b       = (const float*)d_in[10];
    const float* l3_w       = (const float*)d_in[11];
    const float* l3_b       = (const float*)d_in[12];

    float* out = (float*)d_out;

    cudaFuncSetAttribute(gemm_mma_kernel,
                         cudaFuncAttributeMaxDynamicSharedMemorySize, GEMM_SMEM);

    prep_kernel<<<(AGGK*COUT + 255)/256, 256>>>(weight, features, input_pts,
                                                l1_w, l1_b, centers);
    agg_kernel<<<NPTS/8, 128>>>(output_pts, indices, l2_w, l2_b, l3_w, l3_b);
    gemm_mma_kernel<<<NPTS/128, 256, GEMM_SMEM>>>(bias, output_pts, out);
}

// round 16
// speedup vs baseline: 1.4036x; 1.0240x over previous
#include <cuda_runtime.h>
#include <cuda_bf16.h>
#include <cuda_fp16.h>
#include <cstdint>

// Problem constants
#define NB   8
#define NN   8192
#define CIN  64
#define COUT 128
#define KNB  16
#define MM   16
#define NPTS (NB*NN)            // 65536
#define AGGK (CIN*MM)           // 1024

// -------- device scratch --------
__device__ __half g_aggh[(size_t)NPTS * AGGK];   // 134 MB, [p][j], fp16
__device__ __half g_WpTh[(size_t)COUT * AGGK];   // weight^T [n][j], fp16
__device__ float4 g_pts4[NPTS];                  // padded input_pts, 1 MB
__device__ float  g_A1[32*3];
__device__ float  g_c1[32];

// j bijection: c = mt*16 + ih*8 + g ; m = nt*8 + t4*2 + b
// u = ((mt*2+ih)*2 + nt)*32 + g*4 + t4 ; j = 2u + b

// ============================================================
// PTX helpers
// ============================================================
__device__ __forceinline__ uint32_t smem_u32(const void* p) {
    uint32_t a;
    asm("{ .reg .u64 t; cvta.to.shared.u64 t, %1; cvt.u32.u64 %0, t; }" : "=r"(a) : "l"(p));
    return a;
}
__device__ __forceinline__ uint32_t packh2(float a, float b) {
    __half2 h = __floats2half2_rn(a, b);
    return *(uint32_t*)&h;
}
#define CP_ASYNC16(dst, src) \
    asm volatile("cp.async.cg.shared.global [%0], [%1], 16;" :: "r"(dst), "l"(src) : "memory")
#define CP_COMMIT() asm volatile("cp.async.commit_group;" ::: "memory")
#define CP_WAIT1()  asm volatile("cp.async.wait_group 1;" ::: "memory")
#define CP_WAIT0()  asm volatile("cp.async.wait_group 0;" ::: "memory")

__device__ __forceinline__ void ldsm_x4(uint32_t& r0, uint32_t& r1, uint32_t& r2, uint32_t& r3,
                                        uint32_t addr) {
    asm volatile("ldmatrix.sync.aligned.m8n8.x4.shared.b16 {%0,%1,%2,%3}, [%4];"
                 : "=r"(r0), "=r"(r1), "=r"(r2), "=r"(r3) : "r"(addr));
}
__device__ __forceinline__ void mma_f16(float c[4], const uint32_t a[4], const uint32_t b[2]) {
    asm volatile(
        "mma.sync.aligned.m16n8k16.row.col.f32.f16.f16.f32 "
        "{%0,%1,%2,%3}, {%4,%5,%6,%7}, {%8,%9}, {%0,%1,%2,%3};"
        : "+f"(c[0]), "+f"(c[1]), "+f"(c[2]), "+f"(c[3])
        : "r"(a[0]), "r"(a[1]), "r"(a[2]), "r"(a[3]), "r"(b[0]), "r"(b[1]));
}

// ============================================================
// Prep (fused): weight permute + input_pts float4 pack + (block 0)
// layer-1 affine collapse.
// ============================================================
__global__ void prep_kernel(const float* __restrict__ weight,
                            const float* __restrict__ input_pts,
                            const float* __restrict__ l1_w,
                            const float* __restrict__ l1_b,
                            const float* __restrict__ centers)
{
    int e = blockIdx.x * blockDim.x + threadIdx.x;   // 0 .. 131071

    if (e < AGGK * COUT) {
        int n  = e & 127;
        int cm = e >> 7;
        int m  = cm & 15;
        int c  = cm >> 4;
        int gg = c & 7, ih = (c >> 3) & 1, mt = c >> 4;
        int nt = m >> 3, t4 = (m >> 1) & 3, b = m & 1;
        int u  = ((mt*2 + ih)*2 + nt)*32 + gg*4 + t4;
        g_WpTh[(size_t)n*AGGK + 2*u + b] = __float2half_rn(weight[e]);
    }

    if (e < NPTS) {
        g_pts4[e] = make_float4(input_pts[e*3+0], input_pts[e*3+1],
                                input_pts[e*3+2], 0.f);
    }

    if (blockIdx.x == 0 && threadIdx.x < 32) {
        int o = threadIdx.x;
        float a0 = 0.f, a1 = 0.f, a2 = 0.f;
        float c = l1_b[o];
        #pragma unroll
        for (int m = 0; m < MM; m++) {
            float w0 = l1_w[o*48 + 0*16 + m];
            float w1 = l1_w[o*48 + 1*16 + m];
            float w2 = l1_w[o*48 + 2*16 + m];
            a0 += w0; a1 += w1; a2 += w2;
            c -= w0 * centers[0*16 + m];
            c -= w1 * centers[1*16 + m];
            c -= w2 * centers[2*16 + m];
        }
        g_A1[o*3+0] = a0; g_A1[o*3+1] = a1; g_A1[o*3+2] = a2;
        g_c1[o] = c;
    }
}

// ============================================================
// Kernel A (v9 = R13 + occupancy: launch_bounds(128,6), afr hoist
// moved between layers 2 and 3 to shorten its live range).
// ============================================================
#define PH1 40   // halves
#define PH2 24   // halves
#define PDD 20   // floats

__global__ __launch_bounds__(128, 6)
void agg_kernel(const float* __restrict__ features,
                const float* __restrict__ output_pts,
                const int*   __restrict__ indices,
                const float* __restrict__ l2_w, const float* __restrict__ l2_b,
                const float* __restrict__ l3_w, const float* __restrict__ l3_b)
{
    __shared__ __align__(16) float  sA1[96];
    __shared__ __align__(16) float  sC1[32];
    __shared__ __align__(16) __half sH1[4][32*PH1];
    __shared__ __align__(16) __half sH2[4][32*PH2];
    __shared__ __align__(8)  float  sD [4][32*PDD];
    __shared__ int sI[4][2][KNB];

    const int tid = threadIdx.x;
    if (tid < 96)  sA1[tid] = g_A1[tid];
    if (tid < 32)  sC1[tid] = g_c1[tid];
    __syncthreads();

    const int w     = tid >> 5;
    const int lane  = tid & 31;
    const int g     = lane >> 2;
    const int t4    = lane & 3;
    const int q     = lane >> 4;
    const int k     = lane & 15;
    const int pbase = blockIdx.x * 8 + w * 2;
    const int b     = pbase >> 13;
    const float* __restrict__ fb = features + (size_t)b * NN * CIN;

    const int a_r  = (lane & 7) + ((lane >> 3) & 1) * 8;
    const int a_ka = lane >> 4;

    // ---- one-time: W2/W3/bias B-fragments in registers ----
    uint32_t b2[2][2][2], b3[2][2];
    float bs2[2][2], bs3[2][2];
    {
        const int n0 = g, k0 = 2*t4;
        #pragma unroll
        for (int nt = 0; nt < 2; nt++) {
            const int n = nt*8 + n0;
            #pragma unroll
            for (int kc = 0; kc < 2; kc++) {
                b2[kc][nt][0] = packh2(l2_w[n*32 + kc*16 + k0    ], l2_w[n*32 + kc*16 + k0 + 1]);
                b2[kc][nt][1] = packh2(l2_w[n*32 + kc*16 + k0 + 8], l2_w[n*32 + kc*16 + k0 + 9]);
            }
            b3[nt][0] = packh2(l3_w[n*16 + k0    ], l3_w[n*16 + k0 + 1]);
            b3[nt][1] = packh2(l3_w[n*16 + k0 + 8], l3_w[n*16 + k0 + 9]);
            bs2[nt][0] = l2_b[nt*8 + k0];  bs2[nt][1] = l2_b[nt*8 + k0 + 1];
            bs3[nt][0] = l3_b[nt*8 + k0];  bs3[nt][1] = l3_b[nt*8 + k0 + 1];
        }
    }

    __half* H1 = sH1[w];
    __half* H2 = sH2[w];
    float*  Dd = sD[w];
    const uint32_t h1b = smem_u32(H1);
    const uint32_t h2b = smem_u32(H2);

    // ---- layer 1 (FFMA): sample = lane; single float4 point gather ----
    {
        const int p   = pbase + q;
        const int idx = indices[p*KNB + k];
        sI[w][q][k] = idx;
        const float ox = output_pts[p*3+0];
        const float oy = output_pts[p*3+1];
        const float oz = output_pts[p*3+2];
        const float4 P = g_pts4[b*NN + idx];
        const float rx = P.x - ox, ry = P.y - oy, rz = P.z - oz;

        #pragma unroll
        for (int i = 0; i < 8; i++) {
            float v0 = fmaxf(sC1[4*i+0] + sA1[(4*i+0)*3]*rx + sA1[(4*i+0)*3+1]*ry + sA1[(4*i+0)*3+2]*rz, 0.f);
            float v1 = fmaxf(sC1[4*i+1] + sA1[(4*i+1)*3]*rx + sA1[(4*i+1)*3+1]*ry + sA1[(4*i+1)*3+2]*rz, 0.f);
            float v2 = fmaxf(sC1[4*i+2] + sA1[(4*i+2)*3]*rx + sA1[(4*i+2)*3+1]*ry + sA1[(4*i+2)*3+2]*rz, 0.f);
            float v3 = fmaxf(sC1[4*i+3] + sA1[(4*i+3)*3]*rx + sA1[(4*i+3)*3+1]*ry + sA1[(4*i+3)*3+2]*rz, 0.f);
            uint2 pk = make_uint2(packh2(v0, v1), packh2(v2, v3));
            *(uint2*)&H1[lane*PH1 + 4*i] = pk;
        }
    }
    __syncwarp();

    // ---- layer 2: H2[32,16] = relu(H1[32,32] @ W2^T + b2), fp16 mma ----
    {
        float acc2[2][2][4];
        #pragma unroll
        for (int mt = 0; mt < 2; mt++)
            #pragma unroll
            for (int nt = 0; nt < 2; nt++)
                #pragma unroll
                for (int i = 0; i < 4; i++) acc2[mt][nt][i] = 0.f;

        #pragma unroll
        for (int kc = 0; kc < 2; kc++) {
            uint32_t a[2][4];
            #pragma unroll
            for (int mt = 0; mt < 2; mt++) {
                uint32_t addr = h1b + (uint32_t)((mt*16 + a_r)*PH1 + kc*16 + a_ka*8) * 2;
                ldsm_x4(a[mt][0], a[mt][1], a[mt][2], a[mt][3], addr);
            }
            #pragma unroll
            for (int mt = 0; mt < 2; mt++)
                #pragma unroll
                for (int nt = 0; nt < 2; nt++)
                    mma_f16(acc2[mt][nt], a[mt], b2[kc][nt]);
        }
        #pragma unroll
        for (int mt = 0; mt < 2; mt++)
            #pragma unroll
            for (int nt = 0; nt < 2; nt++) {
                const int col = nt*8 + 2*t4;
                *(uint32_t*)&H2[(mt*16 + g    )*PH2 + col] =
                    packh2(fmaxf(acc2[mt][nt][0] + bs2[nt][0], 0.f),
                           fmaxf(acc2[mt][nt][1] + bs2[nt][1], 0.f));
                *(uint32_t*)&H2[(mt*16 + g + 8)*PH2 + col] =
                    packh2(fmaxf(acc2[mt][nt][2] + bs2[nt][0], 0.f),
                           fmaxf(acc2[mt][nt][3] + bs2[nt][1], 0.f));
            }
    }
    __syncwarp();

    // ---- hoisted phase-3 A-fragment gather (both points), fp16 packed ----
    // moved here (after layer 2) to shorten register live range; still
    // overlaps gather latency with layer-3 mma + D stores + B packing.
    uint32_t afr[2][4][4];
    #pragma unroll
    for (int qq = 0; qq < 2; qq++) {
        const float* rA = fb + (size_t)sI[w][qq][2*t4    ] * CIN;
        const float* rB = fb + (size_t)sI[w][qq][2*t4 + 1] * CIN;
        const float* rC = fb + (size_t)sI[w][qq][2*t4 + 8] * CIN;
        const float* rD = fb + (size_t)sI[w][qq][2*t4 + 9] * CIN;
        #pragma unroll
        for (int mt = 0; mt < 4; mt++) {
            const int c0 = mt*16 + g, c1 = mt*16 + g + 8;
            afr[qq][mt][0] = packh2(rA[c0], rB[c0]);
            afr[qq][mt][1] = packh2(rA[c1], rB[c1]);
            afr[qq][mt][2] = packh2(rC[c0], rD[c0]);
            afr[qq][mt][3] = packh2(rC[c1], rD[c1]);
        }
    }

    // ---- layer 3: D[32,16] = relu(H2[32,16] @ W3^T + b3), fp16 mma ----
    {
        float acc3[2][2][4];
        #pragma unroll
        for (int mt = 0; mt < 2; mt++)
            #pragma unroll
            for (int nt = 0; nt < 2; nt++)
                #pragma unroll
                for (int i = 0; i < 4; i++) acc3[mt][nt][i] = 0.f;

        uint32_t a[2][4];
        #pragma unroll
        for (int mt = 0; mt < 2; mt++) {
            uint32_t addr = h2b + (uint32_t)((mt*16 + a_r)*PH2 + a_ka*8) * 2;
            ldsm_x4(a[mt][0], a[mt][1], a[mt][2], a[mt][3], addr);
        }
        #pragma unroll
        for (int mt = 0; mt < 2; mt++)
            #pragma unroll
            for (int nt = 0; nt < 2; nt++)
                mma_f16(acc3[mt][nt], a[mt], b3[nt]);

        #pragma unroll
        for (int mt = 0; mt < 2; mt++)
            #pragma unroll
            for (int nt = 0; nt < 2; nt++) {
                const int col = nt*8 + 2*t4;
                float2 v0 = make_float2(fmaxf(acc3[mt][nt][0] + bs3[nt][0], 0.f),
                                        fmaxf(acc3[mt][nt][1] + bs3[nt][1], 0.f));
                float2 v1 = make_float2(fmaxf(acc3[mt][nt][2] + bs3[nt][0], 0.f),
                                        fmaxf(acc3[mt][nt][3] + bs3[nt][1], 0.f));
                *(float2*)&Dd[(mt*16 + g    )*PDD + col] = v0;
                *(float2*)&Dd[(mt*16 + g + 8)*PDD + col] = v1;
            }
    }
    __syncwarp();

    // ---- phase 3: S = F^T(64x16) @ D(16x16) per point, fp16 k16 mma ----
    #pragma unroll
    for (int qq = 0; qq < 2; qq++) {
        uint32_t bfr[2][2];
        #pragma unroll
        for (int nt = 0; nt < 2; nt++) {
            const int n = nt*8 + g;
            bfr[nt][0] = packh2(Dd[(qq*16 + 2*t4    )*PDD + n],
                                Dd[(qq*16 + 2*t4 + 1)*PDD + n]);
            bfr[nt][1] = packh2(Dd[(qq*16 + 2*t4 + 8)*PDD + n],
                                Dd[(qq*16 + 2*t4 + 9)*PDD + n]);
        }

        float acc[4][2][4];
        #pragma unroll
        for (int mt = 0; mt < 4; mt++)
            #pragma unroll
            for (int nt = 0; nt < 2; nt++)
                #pragma unroll
                for (int i = 0; i < 4; i++) acc[mt][nt][i] = 0.f;

        #pragma unroll
        for (int mt = 0; mt < 4; mt++) {
            mma_f16(acc[mt][0], afr[qq][mt], bfr[0]);
            mma_f16(acc[mt][1], afr[qq][mt], bfr[1]);
        }

        __half2* orow = (__half2*)(g_aggh + (size_t)(pbase + qq) * AGGK);
        #pragma unroll
        for (int mt = 0; mt < 4; mt++) {
            #pragma unroll
            for (int nt = 0; nt < 2; nt++) {
                const int u0 = ((mt*2 + 0)*2 + nt)*32 + lane;
                const int u1 = ((mt*2 + 1)*2 + nt)*32 + lane;
                orow[u0] = __floats2half2_rn(acc[mt][nt][0], acc[mt][nt][1]);
                orow[u1] = __floats2half2_rn(acc[mt][nt][2], acc[mt][nt][3]);
            }
        }
    }
}

// ============================================================
// Kernel B: fp16 mma GEMM (R6/R13 config) + fused output_pts copy.
// ============================================================
#define GBK    64
#define HPITCH 72
#define HTSZ   (128*HPITCH*2)       // 18432 B
#define GSTG   3
#define NCH    (AGGK/GBK)           // 16
#define GEMM_SMEM (GSTG*2*HTSZ + 512)

__global__ __launch_bounds__(256)
void gemm_mma_kernel(const float* __restrict__ bias,
                     const float* __restrict__ output_pts,
                     float* __restrict__ out)
{
    extern __shared__ __align__(16) char smem[];
    float* sbias = (float*)(smem + GSTG*2*HTSZ);

    const int tid  = threadIdx.x;
    const int lane = tid & 31;
    const int warp = tid >> 5;
    const int g    = lane >> 2;
    const int t4   = lane & 3;
    const int m0   = (warp >> 2) * 64;
    const int n0   = (warp & 3) * 32;
    const int p0   = blockIdx.x * 128;

    if (tid < COUT) sbias[tid] = bias[tid];

    const uint32_t smb = smem_u32(smem);
    const __half* gA = g_aggh + (size_t)p0 * AGGK;
    const __half* gB = g_WpTh;

    auto load_chunk = [&](int kc, int st) {
        const uint32_t sa = smb + st*2*HTSZ;
        const uint32_t sb = sa + HTSZ;
        #pragma unroll
        for (int i = 0; i < 4; i++) {
            const int a   = tid + i*256;
            const int row = a >> 3;
            const int ca  = a & 7;
            const uint32_t doff = (uint32_t)(row*HPITCH + ca*8) * 2;
            CP_ASYNC16(sa + doff, gA + (size_t)row*AGGK + kc*GBK + ca*8);
            CP_ASYNC16(sb + doff, gB + (size_t)row*AGGK + kc*GBK + ca*8);
        }
    };

    const int a_r  = (lane & 7) + ((lane >> 3) & 1) * 8;
    const int a_ka = lane >> 4;
    const int b_r  = (lane & 7) + (lane >> 4) * 8;
    const int b_ka = (lane >> 3) & 1;

    float acc[4][4][4];
    #pragma unroll
    for (int mf = 0; mf < 4; mf++)
        #pragma unroll
        for (int nf = 0; nf < 4; nf++)
            #pragma unroll
            for (int i = 0; i < 4; i++) acc[mf][nf][i] = 0.f;

    load_chunk(0, 0); CP_COMMIT();
    load_chunk(1, 1); CP_COMMIT();

    for (int kc = 0; kc < NCH; kc++) {
        const int st = kc % GSTG;
        CP_WAIT1();
        __syncthreads();

        const uint32_t sa = smb + st*2*HTSZ;
        const uint32_t sb = sa + HTSZ;

        #pragma unroll 4
        for (int ks = 0; ks < 4; ks++) {
            uint32_t a[4][4], bb[4][2];
            #pragma unroll
            for (int mf = 0; mf < 4; mf++) {
                uint32_t addr = sa + (uint32_t)((m0 + mf*16 + a_r)*HPITCH
                                + (ks*2 + a_ka)*8) * 2;
                ldsm_x4(a[mf][0], a[mf][1], a[mf][2], a[mf][3], addr);
            }
            #pragma unroll
            for (int np = 0; np < 2; np++) {
                uint32_t addr = sb + (uint32_t)((n0 + np*16 + b_r)*HPITCH
                                + (ks*2 + b_ka)*8) * 2;
                ldsm_x4(bb[np*2][0], bb[np*2][1], bb[np*2+1][0], bb[np*2+1][1], addr);
            }
            #pragma unroll
            for (int mf = 0; mf < 4; mf++)
                #pragma unroll
                for (int nf = 0; nf < 4; nf++)
                    mma_f16(acc[mf][nf], a[mf], bb[nf]);
        }

        if (kc + 2 < NCH) load_chunk(kc + 2, (kc + 2) % GSTG);
        CP_COMMIT();
    }

    const float inv_k = 1.0f / (float)KNB;
    #pragma unroll
    for (int mf = 0; mf < 4; mf++) {
        const int row = p0 + m0 + mf*16 + g;
        #pragma unroll
        for (int nf = 0; nf < 4; nf++) {
            const int col = n0 + nf*8 + t4*2;
            const float b0 = sbias[col], b1 = sbias[col+1];
            float2 v0 = make_float2(acc[mf][nf][0]*inv_k + b0, acc[mf][nf][1]*inv_k + b1);
            float2 v1 = make_float2(acc[mf][nf][2]*inv_k + b0, acc[mf][nf][3]*inv_k + b1);
            *(float2*)(out + (size_t)row*COUT + col)     = v0;
            *(float2*)(out + (size_t)(row+8)*COUT + col) = v1;
        }
    }

    // fused output_pts passthrough: 49152 float4 over 512 CTAs = 96 each
    {
        const float4* src = (const float4*)output_pts;
        float4* dst = (float4*)(out + (size_t)NPTS*COUT);
        const int base = blockIdx.x * 96;
        if (tid < 96) dst[base + tid] = src[base + tid];
    }
}

// ============================================================
extern "C" void kernel_launch(void* const* d_in, const int* in_sizes, int n_in,
                              void* d_out, int out_size)
{
    const float* features   = (const float*)d_in[0];
    const float* input_pts  = (const float*)d_in[1];
    const float* output_pts = (const float*)d_in[2];
    const int*   indices    = (const int*)  d_in[3];
    const float* centers    = (const float*)d_in[4];
    const float* weight     = (const float*)d_in[5];
    const float* bias       = (const float*)d_in[6];
    const float* l1_w       = (const float*)d_in[7];
    const float* l1_b       = (const float*)d_in[8];
    const float* l2_w       = (const float*)d_in[9];
    const float* l2_b       = (const float*)d_in[10];
    const float* l3_w       = (const float*)d_in[11];
    const float* l3_b       = (const float*)d_in[12];

    float* out = (float*)d_out;

    cudaFuncSetAttribute(gemm_mma_kernel,
                         cudaFuncAttributeMaxDynamicSharedMemorySize, GEMM_SMEM);

    prep_kernel<<<(AGGK*COUT + 255)/256, 256>>>(weight, input_pts, l1_w, l1_b, centers);
    agg_kernel<<<NPTS/8, 128>>>(features, output_pts, indices,
                                l2_w, l2_b, l3_w, l3_b);
    gemm_mma_kernel<<<NPTS/128, 256, GEMM_SMEM>>>(bias, output_pts, out);
}